// round 2
// baseline (speedup 1.0000x reference)
#include <cuda_runtime.h>

#define BIN 1025
#define WPB 2   // warps (rows) per block

// FFT-32 twiddles: C32[k] = cos(2*pi*k/32), S32N[k] = -sin(2*pi*k/32)
static __device__ constexpr float C32[16] = {
  1.0f,           0.98078528040f,  0.92387953251f,  0.83146961230f,
  0.70710678119f, 0.55557023302f,  0.38268343236f,  0.19509032202f,
  0.0f,          -0.19509032202f, -0.38268343236f, -0.55557023302f,
 -0.70710678119f,-0.83146961230f, -0.92387953251f, -0.98078528040f
};
static __device__ constexpr float S32N[16] = {
 -0.0f,          -0.19509032202f, -0.38268343236f, -0.55557023302f,
 -0.70710678119f,-0.83146961230f, -0.92387953251f, -0.98078528040f,
 -1.0f,          -0.98078528040f, -0.92387953251f, -0.83146961230f,
 -0.70710678119f,-0.55557023302f, -0.38268343236f, -0.19509032202f
};

// Fully-unrolled radix-2 DIT FFT-32 on register arrays (natural-order in/out).
__device__ __forceinline__ void fft32(float re[32], float im[32]) {
#pragma unroll
  for (int i = 0; i < 32; ++i) {
    const int j = ((i&1)<<4)|((i&2)<<2)|(i&4)|((i&8)>>2)|((i&16)>>4);
    if (j > i) {
      float t = re[i]; re[i] = re[j]; re[j] = t;
      t = im[i]; im[i] = im[j]; im[j] = t;
    }
  }
#pragma unroll
  for (int s = 1; s <= 5; ++s) {
    const int m = 1 << s, half = m >> 1;
#pragma unroll
    for (int g = 0; g < 32; g += m) {
#pragma unroll
      for (int j = 0; j < half; ++j) {
        const float wr = C32[j << (5 - s)];
        const float wi = S32N[j << (5 - s)];
        const int a = g + j, b = a + half;
        const float tr = re[b]*wr - im[b]*wi;
        const float ti = re[b]*wi + im[b]*wr;
        re[b] = re[a] - tr; im[b] = im[a] - ti;
        re[a] = re[a] + tr; im[a] = im[a] + ti;
      }
    }
  }
}

// One symmetric-DFT pass over val[0..1024] (conceptual even-symmetric len-2048 signal).
// FIRST pass: writes L[k] = C[k]*sm[k]*cp[k] back into val.
// Second pass: writes out[k] = C[k]/2048 to global.
// sre/sim: 33-stride scratch planes (conflict-free transposed access).
template<bool FIRST>
__device__ __forceinline__ void sym_pass(float* __restrict__ val,
                                         float* __restrict__ sre,
                                         float* __restrict__ sim,
                                         const int lane,
                                         const float* __restrict__ smrow,
                                         const float* __restrict__ cprow,
                                         float* __restrict__ outrow)
{
  float xr[32], xi[32];
  // Pack: z[m] = a[2m] + i*a[2m+1], where a[j] = val[j<=1024 ? j : 2048-j].
  // Lane b owns m = 32*a + b (four-step column layout).
#pragma unroll
  for (int a = 0; a < 32; ++a) {
    const int m = a * 32 + lane;
    int i0 = 2 * m;     if (i0 > 1024) i0 = 2048 - i0;
    int i1 = 2 * m + 1; if (i1 > 1024) i1 = 2048 - i1;
    xr[a] = val[i0];
    xi[a] = val[i1];
  }
  fft32(xr, xi);  // U[c] = sum_a z[32a+b] * W32^{ac}, b = lane

  // Twiddle by W_1024^{b*c} via rotation recurrence, write transposed V[c][b].
  float wbs, wbc;
  __sincosf(-3.14159265358979f * (float)lane * (1.0f/512.0f), &wbs, &wbc);
  float cr = 1.0f, ci = 0.0f;
#pragma unroll
  for (int c = 0; c < 32; ++c) {
    sre[c*33 + lane] = xr[c]*cr - xi[c]*ci;
    sim[c*33 + lane] = xr[c]*ci + xi[c]*cr;
    const float ncr = cr*wbc - ci*wbs;
    const float nci = cr*wbs + ci*wbc;
    cr = ncr; ci = nci;
  }
  __syncwarp();
#pragma unroll
  for (int b = 0; b < 32; ++b) {
    xr[b] = sre[lane*33 + b];
    xi[b] = sim[lane*33 + b];
  }
  fft32(xr, xi);  // Z[lane + 32*d] in register d
  __syncwarp();   // everyone done reading V before overwrite with Z
#pragma unroll
  for (int d = 0; d < 32; ++d) {
    sre[d*33 + lane] = xr[d];
    sim[d*33 + lane] = xi[d];
  }
  __syncwarp();

  // Unpack real spectrum:
  // C[k] = 0.5*[(A+C) + cos(pi k/1024)*(B+D) - sin(pi k/1024)*(A-C)],
  // where Z[k]=A+iB, Z[1024-k]=C+iD;  C[0]=ReZ0+ImZ0, C[1024]=ReZ0-ImZ0.
  const float z0r = sre[0], z0i = sim[0];
  float s0, c0;
  __sincosf(3.14159265358979f * (float)lane * (1.0f/1024.0f), &s0, &c0);
  const float RC = 0.99518472667220f;   // cos(pi/32)
  const float RS = 0.09801714032956f;   // sin(pi/32)
#pragma unroll
  for (int i = 0; i < 32; ++i) {
    const int k = lane + 32*i;
    float Ck;
    if (k == 0) {
      Ck = z0r + z0i;
    } else {
      const float zkr = sre[i*33 + lane];
      const float zki = sim[i*33 + lane];
      const int k2 = 1024 - k;
      const int o2 = (k2 >> 5)*33 + (k2 & 31);
      const float z2r = sre[o2];
      const float z2i = sim[o2];
      Ck = 0.5f*((zkr + z2r) + c0*(zki + z2i) - s0*(zkr - z2r));
    }
    if (FIRST) val[k] = Ck * smrow[k] * cprow[k];
    else       outrow[k] = Ck * (1.0f/2048.0f);
    const float nc = c0*RC - s0*RS;
    const float ns = s0*RC + c0*RS;
    c0 = nc; s0 = ns;
  }
  if (lane == 0) {
    const float Ck = z0r - z0i;  // k = 1024
    if (FIRST) val[1024] = Ck * smrow[1024] * cprow[1024];
    else       outrow[1024] = Ck * (1.0f/2048.0f);
  }
  __syncwarp();
}

extern "C" __global__ void __launch_bounds__(32 * WPB)
cheptral_kernel(const float* __restrict__ x, const int* __restrict__ f0,
                const float* __restrict__ sm, const float* __restrict__ cp,
                float* __restrict__ out, int nrows)
{
  __shared__ float val_s[WPB][1026];
  __shared__ float sre_s[WPB][33*32];
  __shared__ float sim_s[WPB][33*32];
  const int w    = threadIdx.x >> 5;
  const int lane = threadIdx.x & 31;
  const int row  = blockIdx.x * WPB + w;
  if (row >= nrows) return;

  float* val = val_s[w];
  float* sre = sre_s[w];
  float* sim = sim_s[w];

  const float* xrow = x + (size_t)row * BIN;
  for (int i = lane; i < BIN; i += 32) val[i] = __logf(xrow[i]);
  __syncwarp();

  const int f = f0[row];
  const float* smrow = sm + (size_t)f * BIN;
  const float* cprow = cp + (size_t)f * BIN;

  sym_pass<true >(val, sre, sim, lane, smrow, cprow, nullptr);
  sym_pass<false>(val, sre, sim, lane, nullptr, nullptr, out + (size_t)row * BIN);
}

extern "C" void kernel_launch(void* const* d_in, const int* in_sizes, int n_in,
                              void* d_out, int out_size)
{
  const float* x  = (const float*)d_in[0];
  const int*   f0 = (const int*)d_in[1];
  const float* sm = (const float*)d_in[2];
  const float* cp = (const float*)d_in[3];
  float* out = (float*)d_out;

  const int nrows = in_sizes[1];              // B*T rows
  const int blocks = (nrows + WPB - 1) / WPB;
  cheptral_kernel<<<blocks, 32 * WPB>>>(x, f0, sm, cp, out, nrows);
}